// round 12
// baseline (speedup 1.0000x reference)
#include <cuda_runtime.h>
#include <cuda_bf16.h>
#include <math.h>
#include <stdint.h>

// NT-Xent loss, B=4096, D=256, N=8192.  bf16 HMMA Gram tiles.
//  1) normalize_kernel: zn = z/||z|| bf16 (4 rows/warp, front-loaded loads).
//  2) sim_kernel: triangular 128x128 tiles of zn zn^T via mma.sync bf16.
//     256 threads, 8 warps 2(M)x4(N), warp tile 64x32, cp.async double
//     buffer. Epilogue: exp(2*sim), diag zeroed; tile rowsum ->
//     g_part[bn][m-row], colsum -> g_part[bm][n-row] (unique slots).
//     Positive-band tiles export sim[i,i+B] to g_pos.
//  3) loss_kernel: denom = sum of 64 slots; loss = log(denom) - 2*pos.

#define DIM 256
#define MAXN 8192
#define NT 64            // tile rows (N/128)
#define BK 64

__device__ __nv_bfloat16 g_zn[MAXN * DIM];
__device__ float g_part[NT * MAXN];   // [slot][row]
__device__ float g_pos[MAXN];

__device__ __forceinline__ uint32_t smem_u32(const void* p) {
    uint32_t a;
    asm("{ .reg .u64 t; cvta.to.shared.u64 t, %1; cvt.u32.u64 %0, t; }"
        : "=r"(a) : "l"(p));
    return a;
}

__device__ __forceinline__ void ldsm_x4(uint32_t* r, uint32_t addr) {
    asm volatile("ldmatrix.sync.aligned.m8n8.x4.shared.b16 {%0,%1,%2,%3}, [%4];"
                 : "=r"(r[0]), "=r"(r[1]), "=r"(r[2]), "=r"(r[3]) : "r"(addr));
}

__device__ __forceinline__ void mma16816(float* c, const uint32_t* a,
                                         const uint32_t* b) {
    asm volatile(
        "mma.sync.aligned.m16n8k16.row.col.f32.bf16.bf16.f32 "
        "{%0,%1,%2,%3}, {%4,%5,%6,%7}, {%8,%9}, {%0,%1,%2,%3};"
        : "+f"(c[0]), "+f"(c[1]), "+f"(c[2]), "+f"(c[3])
        : "r"(a[0]), "r"(a[1]), "r"(a[2]), "r"(a[3]), "r"(b[0]), "r"(b[1]));
}

__device__ __forceinline__ void cp_async16(uint32_t saddr, uint64_t gaddr) {
    asm volatile("cp.async.cg.shared.global [%0], [%1], 16;"
                 :: "r"(saddr), "l"(gaddr) : "memory");
}
#define CP_COMMIT() asm volatile("cp.async.commit_group;" ::: "memory")
#define CP_WAIT(n)  asm volatile("cp.async.wait_group %0;" :: "n"(n) : "memory")

// ---------------------------------------------------------------------------
// 1) Normalize -> bf16. 4 rows per warp, loads front-batched for MLP.
// ---------------------------------------------------------------------------
__global__ void normalize_kernel(const float* __restrict__ zi,
                                 const float* __restrict__ zj,
                                 int B, int N, float* out) {
    int tid  = threadIdx.x;
    int warp = tid >> 5;
    int lane = tid & 31;
    int r0   = (blockIdx.x * 8 + warp) * 4;

    if (blockIdx.x == 0 && tid == 0) out[0] = 0.0f;
    if (r0 >= N) return;

    float4 v[4][2];
#pragma unroll
    for (int r = 0; r < 4; r++) {
        int row = r0 + r;
        const float* src = (row < B) ? (zi + (size_t)row * DIM)
                                     : (zj + (size_t)(row - B) * DIM);
        v[r][0] = *reinterpret_cast<const float4*>(src + lane * 8);
        v[r][1] = *reinterpret_cast<const float4*>(src + lane * 8 + 4);
    }

    float ss[4];
#pragma unroll
    for (int r = 0; r < 4; r++)
        ss[r] = v[r][0].x*v[r][0].x + v[r][0].y*v[r][0].y
              + v[r][0].z*v[r][0].z + v[r][0].w*v[r][0].w
              + v[r][1].x*v[r][1].x + v[r][1].y*v[r][1].y
              + v[r][1].z*v[r][1].z + v[r][1].w*v[r][1].w;
#pragma unroll
    for (int off = 16; off > 0; off >>= 1)
#pragma unroll
        for (int r = 0; r < 4; r++)
            ss[r] += __shfl_xor_sync(0xFFFFFFFF, ss[r], off);

#pragma unroll
    for (int r = 0; r < 4; r++) {
        float inv = 1.0f / fmaxf(sqrtf(ss[r]), 1e-8f);
        __nv_bfloat16 h[8];
        h[0] = __float2bfloat16(v[r][0].x * inv);
        h[1] = __float2bfloat16(v[r][0].y * inv);
        h[2] = __float2bfloat16(v[r][0].z * inv);
        h[3] = __float2bfloat16(v[r][0].w * inv);
        h[4] = __float2bfloat16(v[r][1].x * inv);
        h[5] = __float2bfloat16(v[r][1].y * inv);
        h[6] = __float2bfloat16(v[r][1].z * inv);
        h[7] = __float2bfloat16(v[r][1].w * inv);
        *reinterpret_cast<uint4*>(g_zn + (size_t)(r0 + r) * DIM + lane * 8) =
            *reinterpret_cast<uint4*>(h);
    }
}

// ---------------------------------------------------------------------------
// 2) bf16 HMMA Gram-tile kernel. 128x128 tile per block, triangular grid.
//    256 threads: 8 warps 2(M)x4(N), warp tile 64x32. K chunks of 64,
//    cp.async double buffer, XOR-16B swizzle. Dyn smem 64KB.
// ---------------------------------------------------------------------------
__global__ __launch_bounds__(256, 2) void sim_kernel(int nt, int btile) {
    // triangular linear index -> (bm, bn), bn >= bm
    int t = blockIdx.x;
    float f = 2.0f * (float)nt + 1.0f;
    int bm = (int)((f - sqrtf(f * f - 8.0f * (float)t)) * 0.5f);
    while ((bm + 1) * nt - (((bm + 1) * bm) >> 1) <= t) bm++;
    while (bm * nt - ((bm * (bm - 1)) >> 1) > t) bm--;
    int bn = bm + (t - (bm * nt - ((bm * (bm - 1)) >> 1)));

    extern __shared__ char dsm[];
    __shared__ float rowsum[128];
    __shared__ float colsum[128];

    int tid  = threadIdx.x;
    int wid  = tid >> 5;
    int lane = tid & 31;
    int warp_m = wid & 1;      // rows 64*warp_m
    int warp_n = wid >> 1;     // cols 32*warp_n
    int m0 = bm * 128, n0 = bn * 128;
    bool diag = (bm == bn);
    bool postile = (bn - bm == btile);

    if (tid < 128) { rowsum[tid] = 0.0f; colsum[tid] = 0.0f; }

    uint32_t sbase = smem_u32(dsm);
    uint64_t gbase = (uint64_t)__cvta_generic_to_global(g_zn);

    float acc[4][4][4];
#pragma unroll
    for (int mt = 0; mt < 4; mt++)
#pragma unroll
        for (int ntk = 0; ntk < 4; ntk++)
#pragma unroll
            for (int q = 0; q < 4; q++) acc[mt][ntk][q] = 0.0f;

    int a_row = warp_m * 64 + (lane & 15);                         // + mt*16
    int a_ub  = lane >> 4;                                         // + ks*2
    int b_row = warp_n * 32 + ((lane >> 4) & 1) * 8 + (lane & 7);  // + p*16
    int b_ub  = (lane >> 3) & 1;                                   // + ks*2
    int a_sw = a_row & 7, b_sw = b_row & 7;

    auto prefetch = [&](int ch, int buf) {
        uint32_t sb = sbase + (uint32_t)buf * 32768u;
        int kc0 = ch * BK;
#pragma unroll
        for (int it = 0; it < 4; it++) {
            int u = tid + it * 256;              // 0..1023
            int row = u >> 3;
            int kc  = u & 7;
            uint32_t sw = (uint32_t)row * 128u + (uint32_t)((kc ^ (row & 7)) << 4);
            cp_async16(sb + sw,
                       gbase + ((uint64_t)(m0 + row) * DIM + kc0 + kc * 8) * 2u);
            cp_async16(sb + 16384u + sw,
                       gbase + ((uint64_t)(n0 + row) * DIM + kc0 + kc * 8) * 2u);
        }
        CP_COMMIT();
    };

    prefetch(0, 0);

    for (int ch = 0; ch < 4; ch++) {
        int buf = ch & 1;
        if (ch + 1 < 4) {
            prefetch(ch + 1, (ch + 1) & 1);
            CP_WAIT(1);
        } else {
            CP_WAIT(0);
        }
        __syncthreads();

        uint32_t sA = sbase + (uint32_t)buf * 32768u;
        uint32_t sB = sA + 16384u;

#pragma unroll
        for (int ks = 0; ks < 4; ks++) {
            uint32_t ra[4][4];
#pragma unroll
            for (int mt = 0; mt < 4; mt++) {
                int row = a_row + mt * 16;
                int u   = ks * 2 + a_ub;
                ldsm_x4(ra[mt], sA + row * 128 + ((u ^ a_sw) << 4));
            }
#pragma unroll
            for (int p = 0; p < 2; p++) {
                uint32_t rb[4];
                int row = b_row + p * 16;
                int u   = ks * 2 + b_ub;
                ldsm_x4(rb, sB + row * 128 + ((u ^ b_sw) << 4));
#pragma unroll
                for (int mt = 0; mt < 4; mt++) {
                    mma16816(acc[mt][p * 2 + 0], ra[mt], rb + 0);
                    mma16816(acc[mt][p * 2 + 1], ra[mt], rb + 2);
                }
            }
        }
        __syncthreads();
    }

    // ---------------- epilogue ----------------
    int r0 = lane >> 2;            // 0..7
    int c0 = (lane & 3) * 2;       // 0,2,4,6

    float rs[4][2] = {};
    float cs[4][2] = {};

#pragma unroll
    for (int mt = 0; mt < 4; mt++) {
#pragma unroll
        for (int ntk = 0; ntk < 4; ntk++) {
            float e[4];
#pragma unroll
            for (int q = 0; q < 4; q++) {
                int ml = warp_m * 64 + mt * 16 + r0 + (q >> 1) * 8;
                int nl = warp_n * 32 + ntk * 8 + c0 + (q & 1);
                float s = acc[mt][ntk][q];
                if (postile && ml == nl) {
                    g_pos[m0 + ml] = s;
                    g_pos[n0 + nl] = s;
                }
                float v = __expf(2.0f * s);
                if (diag && ml == nl) v = 0.0f;
                e[q] = v;
            }
            rs[mt][0] += e[0] + e[1];
            rs[mt][1] += e[2] + e[3];
            cs[ntk][0] += e[0] + e[2];
            cs[ntk][1] += e[1] + e[3];
        }
    }
#pragma unroll
    for (int mt = 0; mt < 4; mt++)
#pragma unroll
        for (int h = 0; h < 2; h++) {
            float v = rs[mt][h];
            v += __shfl_xor_sync(0xFFFFFFFFu, v, 1);
            v += __shfl_xor_sync(0xFFFFFFFFu, v, 2);
            if ((lane & 3) == 0)
                atomicAdd(&rowsum[warp_m * 64 + mt * 16 + r0 + h * 8], v);
        }
#pragma unroll
    for (int ntk = 0; ntk < 4; ntk++)
#pragma unroll
        for (int h = 0; h < 2; h++) {
            float v = cs[ntk][h];
            v += __shfl_xor_sync(0xFFFFFFFFu, v, 4);
            v += __shfl_xor_sync(0xFFFFFFFFu, v, 8);
            v += __shfl_xor_sync(0xFFFFFFFFu, v, 16);
            if (lane < 4)
                atomicAdd(&colsum[warp_n * 32 + ntk * 8 + c0 + h], v);
        }
    __syncthreads();

    // unique-slot plain stores
    if (tid < 128) {
        g_part[(size_t)bn * MAXN + m0 + tid] = rowsum[tid];
        if (!diag) g_part[(size_t)bm * MAXN + n0 + tid] = colsum[tid];
    }
}

// ---------------------------------------------------------------------------
// 3) Loss: denom = sum of 64 slots; loss = log(denom) - 2*pos.
// ---------------------------------------------------------------------------
__global__ void loss_kernel(int N, float* out) {
    __shared__ float wsum[32];
    int tid  = threadIdx.x;
    int warp = tid >> 5;
    int lane = tid & 31;
    int row  = blockIdx.x * 1024 + tid;

    float d = 0.0f;
#pragma unroll
    for (int s = 0; s < NT; s++)
        d += g_part[(size_t)s * MAXN + row];

    float l = logf(d) - 2.0f * g_pos[row];
#pragma unroll
    for (int off = 16; off > 0; off >>= 1)
        l += __shfl_xor_sync(0xFFFFFFFF, l, off);
    if (lane == 0) wsum[warp] = l;
    __syncthreads();
    if (warp == 0) {
        float v = wsum[lane];
#pragma unroll
        for (int off = 16; off > 0; off >>= 1)
            v += __shfl_xor_sync(0xFFFFFFFF, v, off);
        if (lane == 0) atomicAdd(out, v / (float)N);
    }
}

// ---------------------------------------------------------------------------
extern "C" void kernel_launch(void* const* d_in, const int* in_sizes, int n_in,
                              void* d_out, int out_size) {
    const float* zi = (const float*)d_in[0];
    const float* zj = (const float*)d_in[1];
    int B = in_sizes[0] / DIM;     // 4096
    int N = 2 * B;                 // 8192
    int nt = N / 128;              // 64
    int ntri = nt * (nt + 1) / 2;  // 2080

    cudaFuncSetAttribute(sim_kernel,
                         cudaFuncAttributeMaxDynamicSharedMemorySize, 65536);

    normalize_kernel<<<N / 32, 256>>>(zi, zj, B, N, (float*)d_out);
    sim_kernel<<<ntri, 256, 65536>>>(nt, B / 128);
    loss_kernel<<<N / 1024, 1024>>>(N, (float*)d_out);
}

// round 13
// speedup vs baseline: 1.0005x; 1.0005x over previous
#include <cuda_runtime.h>
#include <cuda_bf16.h>
#include <math.h>
#include <stdint.h>

// NT-Xent loss, B=4096, D=256, N=8192.  bf16 HMMA Gram tiles + PDL overlap.
//  1) normalize_kernel: zn = z/||z|| bf16 (1 row/warp); triggers PDL.
//  2) sim_kernel (PDL on normalize): triangular 128x128 tiles of zn zn^T
//     via mma.sync bf16; 256 threads, 8 warps 2(M)x4(N); cp.async double
//     buffer. Epilogue: exp(2*sim), diag zeroed; rowsum -> g_part[bn][m],
//     colsum -> g_part[bm][n] (unique slots); positive band -> g_pos.
//  3) loss_kernel (PDL on sim): denom = sum of 64 slots;
//     loss = log(denom) - 2*pos; block reduce + atomicAdd.

#define DIM 256
#define MAXN 8192
#define NT 64
#define BK 64

__device__ __nv_bfloat16 g_zn[MAXN * DIM];
__device__ float g_part[NT * MAXN];   // [slot][row]
__device__ float g_pos[MAXN];

__device__ __forceinline__ uint32_t smem_u32(const void* p) {
    uint32_t a;
    asm("{ .reg .u64 t; cvta.to.shared.u64 t, %1; cvt.u32.u64 %0, t; }"
        : "=r"(a) : "l"(p));
    return a;
}

__device__ __forceinline__ void ldsm_x4(uint32_t* r, uint32_t addr) {
    asm volatile("ldmatrix.sync.aligned.m8n8.x4.shared.b16 {%0,%1,%2,%3}, [%4];"
                 : "=r"(r[0]), "=r"(r[1]), "=r"(r[2]), "=r"(r[3]) : "r"(addr));
}

__device__ __forceinline__ void mma16816(float* c, const uint32_t* a,
                                         const uint32_t* b) {
    asm volatile(
        "mma.sync.aligned.m16n8k16.row.col.f32.bf16.bf16.f32 "
        "{%0,%1,%2,%3}, {%4,%5,%6,%7}, {%8,%9}, {%0,%1,%2,%3};"
        : "+f"(c[0]), "+f"(c[1]), "+f"(c[2]), "+f"(c[3])
        : "r"(a[0]), "r"(a[1]), "r"(a[2]), "r"(a[3]), "r"(b[0]), "r"(b[1]));
}

__device__ __forceinline__ void cp_async16(uint32_t saddr, uint64_t gaddr) {
    asm volatile("cp.async.cg.shared.global [%0], [%1], 16;"
                 :: "r"(saddr), "l"(gaddr) : "memory");
}
#define CP_COMMIT() asm volatile("cp.async.commit_group;" ::: "memory")
#define CP_WAIT(n)  asm volatile("cp.async.wait_group %0;" :: "n"(n) : "memory")

#define GDC_WAIT()    asm volatile("griddepcontrol.wait;" ::: "memory")
#define GDC_LAUNCH()  asm volatile("griddepcontrol.launch_dependents;")

// ---------------------------------------------------------------------------
// 1) Normalize -> bf16 (1 row per warp); zero out[0]; trigger dependents.
// ---------------------------------------------------------------------------
__global__ void normalize_kernel(const float* __restrict__ zi,
                                 const float* __restrict__ zj,
                                 int B, int N, float* out) {
    int tid  = threadIdx.x;
    int warp = tid >> 5;
    int lane = tid & 31;
    int row  = blockIdx.x * 8 + warp;

    if (blockIdx.x == 0 && tid == 0) out[0] = 0.0f;

    if (row < N) {
        const float* src = (row < B) ? (zi + (size_t)row * DIM)
                                     : (zj + (size_t)(row - B) * DIM);
        float4 v0 = *reinterpret_cast<const float4*>(src + lane * 8);
        float4 v1 = *reinterpret_cast<const float4*>(src + lane * 8 + 4);
        float ss = v0.x*v0.x + v0.y*v0.y + v0.z*v0.z + v0.w*v0.w
                 + v1.x*v1.x + v1.y*v1.y + v1.z*v1.z + v1.w*v1.w;
#pragma unroll
        for (int off = 16; off > 0; off >>= 1)
            ss += __shfl_xor_sync(0xFFFFFFFF, ss, off);
        float inv = 1.0f / fmaxf(sqrtf(ss), 1e-8f);

        __nv_bfloat16 h[8];
        h[0] = __float2bfloat16(v0.x * inv); h[1] = __float2bfloat16(v0.y * inv);
        h[2] = __float2bfloat16(v0.z * inv); h[3] = __float2bfloat16(v0.w * inv);
        h[4] = __float2bfloat16(v1.x * inv); h[5] = __float2bfloat16(v1.y * inv);
        h[6] = __float2bfloat16(v1.z * inv); h[7] = __float2bfloat16(v1.w * inv);
        *reinterpret_cast<uint4*>(g_zn + (size_t)row * DIM + lane * 8) =
            *reinterpret_cast<uint4*>(h);
    }
    GDC_LAUNCH();
}

// ---------------------------------------------------------------------------
// 2) bf16 HMMA Gram-tile kernel (PDL consumer + producer).
// ---------------------------------------------------------------------------
__global__ __launch_bounds__(256, 2) void sim_kernel(int nt, int btile) {
    // triangular linear index -> (bm, bn), bn >= bm
    int t = blockIdx.x;
    float f = 2.0f * (float)nt + 1.0f;
    int bm = (int)((f - sqrtf(f * f - 8.0f * (float)t)) * 0.5f);
    while ((bm + 1) * nt - (((bm + 1) * bm) >> 1) <= t) bm++;
    while (bm * nt - ((bm * (bm - 1)) >> 1) > t) bm--;
    int bn = bm + (t - (bm * nt - ((bm * (bm - 1)) >> 1)));

    extern __shared__ char dsm[];
    __shared__ float rowsum[128];
    __shared__ float colsum[128];

    int tid  = threadIdx.x;
    int wid  = tid >> 5;
    int lane = tid & 31;
    int warp_m = wid & 1;
    int warp_n = wid >> 1;
    int m0 = bm * 128, n0 = bn * 128;
    bool diag = (bm == bn);
    bool postile = (bn - bm == btile);

    if (tid < 128) { rowsum[tid] = 0.0f; colsum[tid] = 0.0f; }

    uint32_t sbase = smem_u32(dsm);
    uint64_t gbase = (uint64_t)__cvta_generic_to_global(g_zn);

    float acc[4][4][4];
#pragma unroll
    for (int mt = 0; mt < 4; mt++)
#pragma unroll
        for (int ntk = 0; ntk < 4; ntk++)
#pragma unroll
            for (int q = 0; q < 4; q++) acc[mt][ntk][q] = 0.0f;

    int a_row = warp_m * 64 + (lane & 15);
    int a_ub  = lane >> 4;
    int b_row = warp_n * 32 + ((lane >> 4) & 1) * 8 + (lane & 7);
    int b_ub  = (lane >> 3) & 1;
    int a_sw = a_row & 7, b_sw = b_row & 7;

    auto prefetch = [&](int ch, int buf) {
        uint32_t sb = sbase + (uint32_t)buf * 32768u;
        int kc0 = ch * BK;
#pragma unroll
        for (int it = 0; it < 4; it++) {
            int u = tid + it * 256;
            int row = u >> 3;
            int kc  = u & 7;
            uint32_t sw = (uint32_t)row * 128u + (uint32_t)((kc ^ (row & 7)) << 4);
            cp_async16(sb + sw,
                       gbase + ((uint64_t)(m0 + row) * DIM + kc0 + kc * 8) * 2u);
            cp_async16(sb + 16384u + sw,
                       gbase + ((uint64_t)(n0 + row) * DIM + kc0 + kc * 8) * 2u);
        }
        CP_COMMIT();
    };

    GDC_WAIT();           // g_zn must be complete before first read
    prefetch(0, 0);

    for (int ch = 0; ch < 4; ch++) {
        int buf = ch & 1;
        if (ch + 1 < 4) {
            prefetch(ch + 1, (ch + 1) & 1);
            CP_WAIT(1);
        } else {
            CP_WAIT(0);
        }
        __syncthreads();

        uint32_t sA = sbase + (uint32_t)buf * 32768u;
        uint32_t sB = sA + 16384u;

#pragma unroll
        for (int ks = 0; ks < 4; ks++) {
            uint32_t ra[4][4];
#pragma unroll
            for (int mt = 0; mt < 4; mt++) {
                int row = a_row + mt * 16;
                int u   = ks * 2 + a_ub;
                ldsm_x4(ra[mt], sA + row * 128 + ((u ^ a_sw) << 4));
            }
#pragma unroll
            for (int p = 0; p < 2; p++) {
                uint32_t rb[4];
                int row = b_row + p * 16;
                int u   = ks * 2 + b_ub;
                ldsm_x4(rb, sB + row * 128 + ((u ^ b_sw) << 4));
#pragma unroll
                for (int mt = 0; mt < 4; mt++) {
                    mma16816(acc[mt][p * 2 + 0], ra[mt], rb + 0);
                    mma16816(acc[mt][p * 2 + 1], ra[mt], rb + 2);
                }
            }
        }
        __syncthreads();
    }

    GDC_LAUNCH();         // dependents (loss) may begin launching

    // ---------------- epilogue ----------------
    int r0 = lane >> 2;
    int c0 = (lane & 3) * 2;

    float rs[4][2] = {};
    float cs[4][2] = {};

#pragma unroll
    for (int mt = 0; mt < 4; mt++) {
#pragma unroll
        for (int ntk = 0; ntk < 4; ntk++) {
            float e[4];
#pragma unroll
            for (int q = 0; q < 4; q++) {
                int ml = warp_m * 64 + mt * 16 + r0 + (q >> 1) * 8;
                int nl = warp_n * 32 + ntk * 8 + c0 + (q & 1);
                float s = acc[mt][ntk][q];
                if (postile && ml == nl) {
                    g_pos[m0 + ml] = s;
                    g_pos[n0 + nl] = s;
                }
                float v = __expf(2.0f * s);
                if (diag && ml == nl) v = 0.0f;
                e[q] = v;
            }
            rs[mt][0] += e[0] + e[1];
            rs[mt][1] += e[2] + e[3];
            cs[ntk][0] += e[0] + e[2];
            cs[ntk][1] += e[1] + e[3];
        }
    }
#pragma unroll
    for (int mt = 0; mt < 4; mt++)
#pragma unroll
        for (int h = 0; h < 2; h++) {
            float v = rs[mt][h];
            v += __shfl_xor_sync(0xFFFFFFFFu, v, 1);
            v += __shfl_xor_sync(0xFFFFFFFFu, v, 2);
            if ((lane & 3) == 0)
                atomicAdd(&rowsum[warp_m * 64 + mt * 16 + r0 + h * 8], v);
        }
#pragma unroll
    for (int ntk = 0; ntk < 4; ntk++)
#pragma unroll
        for (int h = 0; h < 2; h++) {
            float v = cs[ntk][h];
            v += __shfl_xor_sync(0xFFFFFFFFu, v, 4);
            v += __shfl_xor_sync(0xFFFFFFFFu, v, 8);
            v += __shfl_xor_sync(0xFFFFFFFFu, v, 16);
            if (lane < 4)
                atomicAdd(&colsum[warp_n * 32 + ntk * 8 + c0 + h], v);
        }
    __syncthreads();

    if (tid < 128) {
        g_part[(size_t)bn * MAXN + m0 + tid] = rowsum[tid];
        if (!diag) g_part[(size_t)bm * MAXN + n0 + tid] = colsum[tid];
    }
}

// ---------------------------------------------------------------------------
// 3) Loss (PDL consumer): denom = sum of 64 slots; loss = log(denom)-2*pos.
// ---------------------------------------------------------------------------
__global__ void loss_kernel(int N, float* out) {
    __shared__ float wsum[32];
    int tid  = threadIdx.x;
    int warp = tid >> 5;
    int lane = tid & 31;
    int row  = blockIdx.x * 1024 + tid;

    GDC_WAIT();   // g_part / g_pos complete

    float d = 0.0f;
#pragma unroll
    for (int s = 0; s < NT; s++)
        d += g_part[(size_t)s * MAXN + row];

    float l = logf(d) - 2.0f * g_pos[row];
#pragma unroll
    for (int off = 16; off > 0; off >>= 1)
        l += __shfl_xor_sync(0xFFFFFFFF, l, off);
    if (lane == 0) wsum[warp] = l;
    __syncthreads();
    if (warp == 0) {
        float v = wsum[lane];
#pragma unroll
        for (int off = 16; off > 0; off >>= 1)
            v += __shfl_xor_sync(0xFFFFFFFF, v, off);
        if (lane == 0) atomicAdd(out, v / (float)N);
    }
}

// ---------------------------------------------------------------------------
extern "C" void kernel_launch(void* const* d_in, const int* in_sizes, int n_in,
                              void* d_out, int out_size) {
    const float* zi = (const float*)d_in[0];
    const float* zj = (const float*)d_in[1];
    int B = in_sizes[0] / DIM;     // 4096
    int N = 2 * B;                 // 8192
    int nt = N / 128;              // 64
    int ntri = nt * (nt + 1) / 2;  // 2080

    cudaFuncSetAttribute(sim_kernel,
                         cudaFuncAttributeMaxDynamicSharedMemorySize, 65536);

    normalize_kernel<<<(N + 7) / 8, 256>>>(zi, zj, B, N, (float*)d_out);

    cudaLaunchAttribute pdl[1];
    pdl[0].id = cudaLaunchAttributeProgrammaticStreamSerialization;
    pdl[0].val.programmaticStreamSerializationAllowed = 1;

    {
        cudaLaunchConfig_t cfg = {};
        cfg.gridDim = dim3(ntri, 1, 1);
        cfg.blockDim = dim3(256, 1, 1);
        cfg.dynamicSmemBytes = 65536;
        cfg.stream = 0;
        cfg.attrs = pdl;
        cfg.numAttrs = 1;
        cudaLaunchKernelEx(&cfg, sim_kernel, nt, B / 128);
    }
    {
        cudaLaunchConfig_t cfg = {};
        cfg.gridDim = dim3(N / 1024, 1, 1);
        cfg.blockDim = dim3(1024, 1, 1);
        cfg.dynamicSmemBytes = 0;
        cfg.stream = 0;
        cfg.attrs = pdl;
        cfg.numAttrs = 1;
        cudaLaunchKernelEx(&cfg, loss_kernel, N, (float*)d_out);
    }
}